// round 3
// baseline (speedup 1.0000x reference)
#include <cuda_runtime.h>
#include <math.h>

// Fully-fused Sherman–Morrison delta-rule update.
// out[b,o,:] = W[b,o,:] - scale_b * (W[b,o,:]·x_b - g[b,o]) * x_b
// scale_b = 1/(1024 + softplus(x_b·eta_w + eta_b))
//
// One warp per output row, 8 rows per 256-thread block.
// scale_b is recomputed redundantly PER WARP (eta_w is 4KB, cache-resident),
// so after the single x-staging sync every warp runs load->dot->store
// independently — no cross-warp coupling on the long-latency path.
__global__ __launch_bounds__(256) void sm_update_fused_kernel(
    const float* __restrict__ W,
    const float* __restrict__ x,
    const float* __restrict__ grad,
    const float* __restrict__ eta_w,
    const float* __restrict__ eta_b,
    float* __restrict__ out) {

    __shared__ float4 xs[256];   // x_b: 1024 floats

    const int b = blockIdx.x >> 7;        // 128 blocks per batch
    const int ochunk = blockIdx.x & 127;
    const int t = threadIdx.x;
    const int warp = t >> 5;
    const int lane = t & 31;

    // stage x_b (only block-wide sync in the kernel)
    xs[t] = reinterpret_cast<const float4*>(x + (size_t)b * 1024)[t];
    __syncthreads();

    const int o = (ochunk << 3) + warp;
    const size_t row_off = ((size_t)b * 1024 + o) * 1024;
    const float4* wrow = reinterpret_cast<const float4*>(W + row_off);

    // Issue all 8 W-row loads first (max MLP), ...
    float4 wv[8];
#pragma unroll
    for (int k = 0; k < 8; k++)
        wv[k] = wrow[(k << 5) + lane];

    // ... then compute the warp-local eta dot while those loads are in flight.
    float ep = 0.0f;
#pragma unroll
    for (int k = 0; k < 8; k++) {
        const int idx = (k << 5) + lane;
        const float4 ew = __ldg(reinterpret_cast<const float4*>(eta_w) + idx);
        const float4 xv = xs[idx];
        ep += ew.x * xv.x + ew.y * xv.y + ew.z * xv.z + ew.w * xv.w;
    }
    for (int off = 16; off; off >>= 1)
        ep += __shfl_xor_sync(0xffffffffu, ep, off);
    const float z = ep + __ldg(eta_b);
    const float sp = fmaxf(z, 0.0f) + log1pf(expf(-fabsf(z)));
    const float scale = 1.0f / (1024.0f + sp);

    // W-row dot with x_b
    float dot = 0.0f;
#pragma unroll
    for (int k = 0; k < 8; k++) {
        const int idx = (k << 5) + lane;
        const float4 xv = xs[idx];
        dot += wv[k].x * xv.x + wv[k].y * xv.y + wv[k].z * xv.z + wv[k].w * xv.w;
    }
    for (int off = 16; off; off >>= 1)
        dot += __shfl_xor_sync(0xffffffffu, dot, off);

    const float err = dot - grad[(size_t)b * 1024 + o];
    const float se = scale * err;

    float4* orow = reinterpret_cast<float4*>(out + row_off);
#pragma unroll
    for (int k = 0; k < 8; k++) {
        const int idx = (k << 5) + lane;
        const float4 xv = xs[idx];
        float4 r;
        r.x = wv[k].x - se * xv.x;
        r.y = wv[k].y - se * xv.y;
        r.z = wv[k].z - se * xv.z;
        r.w = wv[k].w - se * xv.w;
        orow[idx] = r;
    }
}

extern "C" void kernel_launch(void* const* d_in, const int* in_sizes, int n_in,
                              void* d_out, int out_size) {
    // metadata order: W_t [128,1024,1024], x_t [128,1024], grad_l_in [128,1024],
    //                 eta_w [1,1024], eta_b [1]
    const float* W     = (const float*)d_in[0];
    const float* x     = (const float*)d_in[1];
    const float* grad  = (const float*)d_in[2];
    const float* eta_w = (const float*)d_in[3];
    const float* eta_b = (const float*)d_in[4];
    float* out = (float*)d_out;

    sm_update_fused_kernel<<<128 * 128, 256>>>(W, x, grad, eta_w, eta_b, out);
}

// round 4
// speedup vs baseline: 1.0040x; 1.0040x over previous
#include <cuda_runtime.h>
#include <math.h>

// Per-batch learning-rate scale (device-global scratch — no allocs allowed).
__device__ float g_scale[128];

// scale[b] = 1 / (1024 + softplus(dot(x_b, eta_w) + eta_b))
__global__ void eta_scale_kernel(const float* __restrict__ x,
                                 const float* __restrict__ eta_w,
                                 const float* __restrict__ eta_b) {
    const int b = blockIdx.x;
    const float* xb = x + (size_t)b * 1024;

    float partial = 0.0f;
    for (int i = threadIdx.x; i < 1024; i += blockDim.x)
        partial += xb[i] * eta_w[i];

    for (int off = 16; off; off >>= 1)
        partial += __shfl_xor_sync(0xffffffffu, partial, off);

    __shared__ float red[8];
    const int warp = threadIdx.x >> 5;
    const int lane = threadIdx.x & 31;
    if (lane == 0) red[warp] = partial;
    __syncthreads();

    if (threadIdx.x == 0) {
        float s = 0.0f;
        const int nw = blockDim.x >> 5;
        for (int w = 0; w < nw; w++) s += red[w];
        const float z = s + eta_b[0];
        const float sp = fmaxf(z, 0.0f) + log1pf(expf(-fabsf(z)));
        g_scale[b] = 1.0f / (1024.0f + sp);
    }
}

// Streaming update: one warp per output row, 8 rows per 256-thread block.
// No eta traffic in this kernel — it reads g_scale only AFTER the grid
// dependency sync, so all W-load/dot work overlaps the eta kernel via PDL.
__global__ __launch_bounds__(256) void sm_update_kernel(
    const float* __restrict__ W,
    const float* __restrict__ x,
    const float* __restrict__ grad,
    float* __restrict__ out) {

    __shared__ float4 xs[256];  // x_b as 256 float4 = 1024 floats

    const int b = blockIdx.x >> 7;        // 128 blocks per batch
    const int ochunk = blockIdx.x & 127;
    const int t = threadIdx.x;
    const int warp = t >> 5;
    const int lane = t & 31;

    // stage x_b
    xs[t] = reinterpret_cast<const float4*>(x + (size_t)b * 1024)[t];
    __syncthreads();

    const int o = (ochunk << 3) + warp;
    const size_t row_off = ((size_t)b * 1024 + o) * 1024;
    const float4* wrow = reinterpret_cast<const float4*>(W + row_off);

    float4 wv[8];
    float dot = 0.0f;
#pragma unroll
    for (int k = 0; k < 8; k++) {
        const int idx = (k << 5) + lane;
        wv[k] = wrow[idx];
        const float4 xv = xs[idx];
        dot += wv[k].x * xv.x + wv[k].y * xv.y + wv[k].z * xv.z + wv[k].w * xv.w;
    }

    for (int off = 16; off; off >>= 1)
        dot += __shfl_xor_sync(0xffffffffu, dot, off);

    const float g = grad[(size_t)b * 1024 + o];

#if __CUDA_ARCH__ >= 900
    // Wait for the eta kernel (PDL): everything above is independent of it.
    cudaGridDependencySynchronize();
#endif

    const float se = g_scale[b] * (dot - g);

    float4* orow = reinterpret_cast<float4*>(out + row_off);
#pragma unroll
    for (int k = 0; k < 8; k++) {
        const int idx = (k << 5) + lane;
        const float4 xv = xs[idx];
        float4 r;
        r.x = wv[k].x - se * xv.x;
        r.y = wv[k].y - se * xv.y;
        r.z = wv[k].z - se * xv.z;
        r.w = wv[k].w - se * xv.w;
        orow[idx] = r;
    }
}

extern "C" void kernel_launch(void* const* d_in, const int* in_sizes, int n_in,
                              void* d_out, int out_size) {
    // metadata order: W_t [128,1024,1024], x_t [128,1024], grad_l_in [128,1024],
    //                 eta_w [1,1024], eta_b [1]
    const float* W     = (const float*)d_in[0];
    const float* x     = (const float*)d_in[1];
    const float* grad  = (const float*)d_in[2];
    const float* eta_w = (const float*)d_in[3];
    const float* eta_b = (const float*)d_in[4];
    float* out = (float*)d_out;

    eta_scale_kernel<<<128, 256>>>(x, eta_w, eta_b);

    // Launch the streaming kernel with programmatic stream serialization so
    // it overlaps the (tiny) eta kernel; device side gates on
    // cudaGridDependencySynchronize before reading g_scale.
    cudaLaunchConfig_t cfg = {};
    cfg.gridDim = dim3(128 * 128);
    cfg.blockDim = dim3(256);
    cfg.dynamicSmemBytes = 0;
    cfg.stream = 0;
    cudaLaunchAttribute attrs[1];
    attrs[0].id = cudaLaunchAttributeProgrammaticStreamSerialization;
    attrs[0].val.programmaticStreamSerializationAllowed = 1;
    cfg.attrs = attrs;
    cfg.numAttrs = 1;

    cudaError_t e = cudaLaunchKernelEx(&cfg, sm_update_kernel, W, x, grad, out);
    if (e != cudaSuccess) {
        // Fallback: plain stream-ordered launch (still correct, just serial).
        sm_update_kernel<<<128 * 128, 256>>>(W, x, grad, out);
    }
}